// round 13
// baseline (speedup 1.0000x reference)
#include <cuda_runtime.h>
#include <math.h>
#include <stdint.h>

// Problem constants
#define EDIM 1024
#define HN   16
#define DHD  64
#define DFFD 4096
#define NLE  4
#define NLD  4
#define NB   4
#define SEQ  512
#define NROWS (NB*SEQ)     // 2048
#define NBH   (NB*HN)      // 64
#define QKVOFF (NBH*SEQ*DHD)   // one q/k/v slab: 64*512*64 = 2M floats

// tf32-rounded weight slab offsets (floats)
#define W_EQKV 0LL
#define W_EWO  12582912LL
#define W_EW1  16777216LL
#define W_EW2  33554432LL
#define W_DQS  50331648LL
#define W_DWOS 62914560LL
#define W_DQC  67108864LL
#define W_DWOC 79691776LL
#define W_DW1  83886080LL
#define W_DW2  100663296LL
#define W_TOT  117440512LL

// ---------------- scratch (static device globals; no allocations) ----------
__device__ float g_x  [NB*SEQ*EDIM];
__device__ float g_y  [NB*SEQ*EDIM];
__device__ float g_xr [NB*SEQ*EDIM];              // tf32-rounded copy of x
__device__ float g_yr [NB*SEQ*EDIM];              // tf32-rounded copy of y
__device__ float g_qkv[3*QKVOFF];                 // q|k|v, each (B,H,S,DH)
__device__ float g_t1 [NB*SEQ*EDIM];              // flash out (pre-rounded)
__device__ float g_t2 [NB*SEQ*EDIM];
__device__ float g_ff [NB*SEQ*DFFD];              // relu out (pre-rounded)
__device__ float g_wtf[W_TOT];                    // tf32-rounded weights

// ---------------- small helpers ---------------------------------------------
__device__ __forceinline__ uint32_t f2tf(float x) {
    uint32_t r; asm("cvt.rna.tf32.f32 %0, %1;" : "=r"(r) : "f"(x)); return r;
}
__device__ __forceinline__ float tfr(float x) { return __uint_as_float(f2tf(x)); }
__device__ __forceinline__ uint4 cvt4(float4 v) {
    return make_uint4(f2tf(v.x), f2tf(v.y), f2tf(v.z), f2tf(v.w));
}
__device__ __forceinline__ void mma_tf32(float* c, const uint32_t* a, const uint32_t* b) {
    asm volatile("mma.sync.aligned.m16n8k8.row.col.f32.tf32.tf32.f32 "
                 "{%0,%1,%2,%3},{%4,%5,%6,%7},{%8,%9},{%0,%1,%2,%3};"
                 : "+f"(c[0]), "+f"(c[1]), "+f"(c[2]), "+f"(c[3])
                 : "r"(a[0]), "r"(a[1]), "r"(a[2]), "r"(a[3]), "r"(b[0]), "r"(b[1]));
}
__device__ __forceinline__ void cp_async16(uint32_t dst, const void* src) {
    asm volatile("cp.async.cg.shared.global [%0], [%1], 16;\n" :: "r"(dst), "l"(src));
}
__device__ __forceinline__ void cp_async8(uint32_t dst, const void* src) {
    asm volatile("cp.async.ca.shared.global [%0], [%1], 8;\n" :: "r"(dst), "l"(src));
}
__device__ __forceinline__ void cp_commit() {
    asm volatile("cp.async.commit_group;\n");
}
template<int N>
__device__ __forceinline__ void cp_wait() {
    asm volatile("cp.async.wait_group %0;\n" :: "n"(N));
}

__device__ __forceinline__ float blockReduceSum(float v) {
    __shared__ float sh[32];
    int lane = threadIdx.x & 31, w = threadIdx.x >> 5, nw = blockDim.x >> 5;
    #pragma unroll
    for (int o = 16; o; o >>= 1) v += __shfl_xor_sync(0xffffffffu, v, o);
    if (lane == 0) sh[w] = v;
    __syncthreads();
    if (w == 0) {
        float t = (lane < nw) ? sh[lane] : 0.f;
        #pragma unroll
        for (int o = 16; o; o >>= 1) t += __shfl_xor_sync(0xffffffffu, t, o);
        if (lane == 0) sh[0] = t;
    }
    __syncthreads();
    float r = sh[0]; __syncthreads(); return r;
}

// ---------------- merged tf32 round-copy of ALL weights (one launch) --------
__global__ void roundcopy_all_k(const float* __restrict__ eqkv, const float* __restrict__ ewo,
                                const float* __restrict__ ew1,  const float* __restrict__ ew2,
                                const float* __restrict__ dqs,  const float* __restrict__ dwos,
                                const float* __restrict__ dqc,  const float* __restrict__ dwoc,
                                const float* __restrict__ dw1,  const float* __restrict__ dw2,
                                float* __restrict__ out)
{
    const long long n4 = W_TOT / 4;
    for (long long i = blockIdx.x * blockDim.x + threadIdx.x; i < n4;
         i += (long long)gridDim.x * blockDim.x) {
        long long e = i * 4;
        const float* src; long long off;
        if      (e < W_EWO)  { src = eqkv; off = e - W_EQKV; }
        else if (e < W_EW1)  { src = ewo;  off = e - W_EWO;  }
        else if (e < W_EW2)  { src = ew1;  off = e - W_EW1;  }
        else if (e < W_DQS)  { src = ew2;  off = e - W_EW2;  }
        else if (e < W_DWOS) { src = dqs;  off = e - W_DQS;  }
        else if (e < W_DQC)  { src = dwos; off = e - W_DWOS; }
        else if (e < W_DWOC) { src = dqc;  off = e - W_DQC;  }
        else if (e < W_DW1)  { src = dwoc; off = e - W_DWOC; }
        else if (e < W_DW2)  { src = dw1;  off = e - W_DW1;  }
        else                 { src = dw2;  off = e - W_DW2;  }
        float4 v = *(const float4*)(src + off);
        ((float4*)out)[i] = make_float4(tfr(v.x), tfr(v.y), tfr(v.z), tfr(v.w));
    }
}

// ---------------- layout swap (S,B,E) <-> (B,S,E) ---------------------------
__global__ void reorder_k(const float* __restrict__ in, float* __restrict__ out,
                          float* __restrict__ outr, int toBS) {
    int s = blockIdx.x, b = blockIdx.y;
    long long r_sb = ((long long)s * NB + b) * EDIM;
    long long r_bs = ((long long)b * SEQ + s) * EDIM;
    long long ro = toBS ? r_bs : r_sb;
    const float4* src = (const float4*)(in + (toBS ? r_sb : r_bs));
    float4*       dst = (float4*)(out + ro);
    float4*       dstr = outr ? (float4*)(outr + ro) : nullptr;
    for (int i = threadIdx.x; i < EDIM / 4; i += blockDim.x) {
        float4 v = src[i];
        dst[i] = v;
        if (dstr) dstr[i] = make_float4(tfr(v.x), tfr(v.y), tfr(v.z), tfr(v.w));
    }
}

// ---------------- TF32 tensor-core GEMM, 5-stage cp.async pipeline ----------
// Inputs A and Bm MUST be pre-rounded to tf32 (raw bits fed to MMA).
// bMode: 0 = B row-major [k*ldb + n]; 1 = head-sliced weight (n>>6)*K*64+k*64+(n&63)
// cMode: 0 = C[m*ldc + n]; 1 = qkv scatter (+nOff) into unified (3,B,H,S,DH)
template<int BM, int BN, int BK, int STG, int WGN, int MT, int NT, int bMode>
__global__ __launch_bounds__(256, 2)
void tmma_k(const float* __restrict__ A, const float* __restrict__ Bm,
            const float* __restrict__ bias, float* __restrict__ C,
            int M, int N, int K, int lda, int ldb, int ldc,
            int cMode, int relu, int rOut, int nOff, float scale)
{
    constexpr int SAS   = BK + 4;
    constexpr int SBS   = BN + 8;
    constexpr int A_PER = (BM * BK) / 256;
    constexpr int STG_A = BM * SAS;
    constexpr int STG_B = BK * SBS;

    extern __shared__ float smem[];
    float* sA = smem;                    // [STG][STG_A]
    float* sB = smem + STG * STG_A;      // [STG][STG_B]

    const int tid = threadIdx.x;
    const int row0 = blockIdx.y * BM, col0 = blockIdx.x * BN;
    const int w = tid >> 5, lane = tid & 31;
    const int gid = lane >> 2, tig = lane & 3;
    const int wm = w / WGN, wn = w % WGN;
    const int mBase = wm * MT * 16, nBase = wn * NT * 8;

    const int arA = (tid * A_PER) / BK, acA = (tid * A_PER) % BK;
    const int brB = (tid * 4) / BN,    bcB = (tid * 4) % BN;
    const float* aSrc = A + (long long)(row0 + arA) * lda + acA;
    const float* bSrc;
    if (bMode == 1) {
        int n = col0 + bcB; int h = n >> 6, dl = n & 63;
        bSrc = Bm + (long long)h * K * 64 + (long long)brB * 64 + dl;
    } else {
        bSrc = Bm + (long long)brB * ldb + col0 + bcB;
    }
    const long long bStep = (bMode == 0) ? (long long)BK * ldb : (long long)BK * 64;

    const uint32_t sAu = (uint32_t)__cvta_generic_to_shared(sA)
                       + (uint32_t)(arA * SAS + acA) * 4u;
    const uint32_t sBu = (uint32_t)__cvta_generic_to_shared(sB)
                       + (uint32_t)(brB * SBS + bcB) * 4u;

    float acc[MT][NT][4];
    #pragma unroll
    for (int i = 0; i < MT; i++)
        #pragma unroll
        for (int j = 0; j < NT; j++)
            #pragma unroll
            for (int r = 0; r < 4; r++) acc[i][j][r] = 0.f;

    const int nit = K / BK;

    #pragma unroll
    for (int s = 0; s < STG - 1; s++) {
        if (s < nit) {
            if (A_PER == 4) cp_async16(sAu + s * STG_A * 4, aSrc + s * BK);
            else            cp_async8 (sAu + s * STG_A * 4, aSrc + s * BK);
            cp_async16(sBu + s * STG_B * 4, bSrc + (long long)s * bStep);
        }
        cp_commit();
    }

    for (int it = 0; it < nit; it++) {
        cp_wait<STG - 2>();
        __syncthreads();

        const int buf = it % STG;
        const uint32_t* sAf = (const uint32_t*)(sA + buf * STG_A);
        const uint32_t* sBf = (const uint32_t*)(sB + buf * STG_B);

        uint32_t af[MT][4], bf[NT][2];
        #pragma unroll
        for (int mt = 0; mt < MT; mt++) {
            int m0 = mBase + mt * 16;
            af[mt][0] = sAf[(m0 + gid)     * SAS + tig];
            af[mt][1] = sAf[(m0 + gid + 8) * SAS + tig];
            af[mt][2] = sAf[(m0 + gid)     * SAS + tig + 4];
            af[mt][3] = sAf[(m0 + gid + 8) * SAS + tig + 4];
        }
        #pragma unroll
        for (int nt = 0; nt < NT; nt++) {
            int n0 = nBase + nt * 8;
            bf[nt][0] = sBf[tig       * SBS + n0 + gid];
            bf[nt][1] = sBf[(tig + 4) * SBS + n0 + gid];
        }
        #pragma unroll
        for (int mt = 0; mt < MT; mt++)
            #pragma unroll
            for (int nt = 0; nt < NT; nt++)
                mma_tf32(acc[mt][nt], af[mt], bf[nt]);

        const int nx = it + STG - 1;
        if (nx < nit) {
            const int nb = nx % STG;
            if (A_PER == 4) cp_async16(sAu + nb * STG_A * 4, aSrc + (long long)nx * BK);
            else            cp_async8 (sAu + nb * STG_A * 4, aSrc + (long long)nx * BK);
            cp_async16(sBu + nb * STG_B * 4, bSrc + (long long)nx * bStep);
        }
        cp_commit();
    }
    cp_wait<0>();   // drain before CTA exit

    #pragma unroll
    for (int mt = 0; mt < MT; mt++) {
        #pragma unroll
        for (int h2 = 0; h2 < 2; h2++) {
            int m = row0 + mBase + mt * 16 + gid + h2 * 8;
            #pragma unroll
            for (int nt = 0; nt < NT; nt++) {
                int n = col0 + nBase + nt * 8 + tig * 2;
                float v0 = acc[mt][nt][h2 * 2 + 0] * scale;
                float v1 = acc[mt][nt][h2 * 2 + 1] * scale;
                if (bias) { v0 += bias[n]; v1 += bias[n + 1]; }
                if (relu) { v0 = fmaxf(v0, 0.f); v1 = fmaxf(v1, 0.f); }
                if (rOut) { v0 = tfr(v0); v1 = tfr(v1); }
                if (cMode == 0) {
                    *(float2*)&C[(long long)m * ldc + n] = make_float2(v0, v1);
                } else {
                    int nq = n + nOff;
                    int which = nq >> 10, h = (nq >> 6) & 15;
                    int b = m >> 9, s = m & 511, d = n & 63;
                    *(float2*)&C[(long long)which * QKVOFF
                        + (((long long)(b * HN + h)) * SEQ + s) * DHD + d] = make_float2(v0, v1);
                }
            }
        }
    }
}

// ---------------- fused flash attention --------------------------------------
#define SKS 68
#define SVS 72
template<int CAUSAL>
__global__ __launch_bounds__(256, 2)
void flash_k(const float* __restrict__ q, const float* __restrict__ k,
             const float* __restrict__ v, const float* __restrict__ pad,
             float* __restrict__ out)
{
    __shared__ uint32_t sK[64 * SKS];
    __shared__ uint32_t sV[64 * SVS];
    __shared__ float sPad[64];

    const int tid  = threadIdx.x;
    const int w    = tid >> 5, lane = tid & 31;
    const int gid  = lane >> 2, tig = lane & 3;
    const int bh   = blockIdx.y;
    const int b    = bh >> 4, h = bh & 15;
    const int qbase = blockIdx.x * 128 + w * 16;
    const int row0 = qbase + gid, row1 = row0 + 8;

    uint32_t qf[8][4];
    {
        const float* qp = q + ((long long)bh * SEQ) * DHD;
        #pragma unroll
        for (int kk = 0; kk < 8; kk++) {
            qf[kk][0] = f2tf(0.125f * qp[(long long)row0 * DHD + kk * 8 + tig]);
            qf[kk][1] = f2tf(0.125f * qp[(long long)row1 * DHD + kk * 8 + tig]);
            qf[kk][2] = f2tf(0.125f * qp[(long long)row0 * DHD + kk * 8 + tig + 4]);
            qf[kk][3] = f2tf(0.125f * qp[(long long)row1 * DHD + kk * 8 + tig + 4]);
        }
    }

    float oacc[8][4];
    #pragma unroll
    for (int nt = 0; nt < 8; nt++)
        #pragma unroll
        for (int r = 0; r < 4; r++) oacc[nt][r] = 0.f;
    float m0 = -INFINITY, m1 = -INFINITY, l0 = 0.f, l1 = 0.f;

    const int Tend = CAUSAL ? (blockIdx.x * 128 + 128) : SEQ;

    for (int t0 = 0; t0 < Tend; t0 += 64) {
        {
            const float* kp = k + ((long long)bh * SEQ + t0) * DHD;
            const float* vp = v + ((long long)bh * SEQ + t0) * DHD;
            #pragma unroll
            for (int i = 0; i < 4; i++) {
                int e = (i * 256 + tid) * 4;
                int t = e >> 6, d = e & 63;
                float4 kv = *(const float4*)(kp + (long long)t * DHD + d);
                *(uint4*)&sK[t * SKS + d] = cvt4(kv);
                float4 vv = *(const float4*)(vp + (long long)t * DHD + d);
                *(uint4*)&sV[t * SVS + d] = cvt4(vv);
            }
            if (tid < 64) sPad[tid] = pad ? pad[b * SEQ + t0 + tid] : 0.f;
        }
        __syncthreads();

        float s[8][4];
        #pragma unroll
        for (int nt = 0; nt < 8; nt++)
            #pragma unroll
            for (int r = 0; r < 4; r++) s[nt][r] = 0.f;
        #pragma unroll
        for (int kk = 0; kk < 8; kk++) {
            #pragma unroll
            for (int nt = 0; nt < 8; nt++) {
                uint32_t bf[2];
                bf[0] = sK[(nt * 8 + gid) * SKS + kk * 8 + tig];
                bf[1] = sK[(nt * 8 + gid) * SKS + kk * 8 + tig + 4];
                mma_tf32(s[nt], qf[kk], bf);
            }
        }

        #pragma unroll
        for (int nt = 0; nt < 8; nt++) {
            int c0 = nt * 8 + 2 * tig, c1 = c0 + 1;
            float p0 = sPad[c0], p1 = sPad[c1];
            s[nt][0] += p0; s[nt][1] += p1;
            s[nt][2] += p0; s[nt][3] += p1;
            if (CAUSAL) {
                int tc0 = t0 + c0, tc1 = t0 + c1;
                if (tc0 > row0) s[nt][0] = -INFINITY;
                if (tc1 > row0) s[nt][1] = -INFINITY;
                if (tc0 > row1) s[nt][2] = -INFINITY;
                if (tc1 > row1) s[nt][3] = -INFINITY;
            }
        }

        float mt0 = -INFINITY, mt1 = -INFINITY;
        #pragma unroll
        for (int nt = 0; nt < 8; nt++) {
            mt0 = fmaxf(mt0, fmaxf(s[nt][0], s[nt][1]));
            mt1 = fmaxf(mt1, fmaxf(s[nt][2], s[nt][3]));
        }
        mt0 = fmaxf(mt0, __shfl_xor_sync(0xffffffffu, mt0, 1));
        mt0 = fmaxf(mt0, __shfl_xor_sync(0xffffffffu, mt0, 2));
        mt1 = fmaxf(mt1, __shfl_xor_sync(0xffffffffu, mt1, 1));
        mt1 = fmaxf(mt1, __shfl_xor_sync(0xffffffffu, mt1, 2));
        float mn0 = fmaxf(m0, mt0), mn1 = fmaxf(m1, mt1);
        float sc0 = __expf(m0 - mn0), sc1 = __expf(m1 - mn1);

        float rs0 = 0.f, rs1 = 0.f;
        #pragma unroll
        for (int nt = 0; nt < 8; nt++) {
            s[nt][0] = __expf(s[nt][0] - mn0);
            s[nt][1] = __expf(s[nt][1] - mn0);
            s[nt][2] = __expf(s[nt][2] - mn1);
            s[nt][3] = __expf(s[nt][3] - mn1);
            rs0 += s[nt][0] + s[nt][1];
            rs1 += s[nt][2] + s[nt][3];
        }
        rs0 += __shfl_xor_sync(0xffffffffu, rs0, 1);
        rs0 += __shfl_xor_sync(0xffffffffu, rs0, 2);
        rs1 += __shfl_xor_sync(0xffffffffu, rs1, 1);
        rs1 += __shfl_xor_sync(0xffffffffu, rs1, 2);
        l0 = l0 * sc0 + rs0;
        l1 = l1 * sc1 + rs1;
        m0 = mn0; m1 = mn1;
        #pragma unroll
        for (int nt = 0; nt < 8; nt++) {
            oacc[nt][0] *= sc0; oacc[nt][1] *= sc0;
            oacc[nt][2] *= sc1; oacc[nt][3] *= sc1;
        }

        const int qlane = lane & ~3;
        const int sl0 = qlane | (tig >> 1);
        const int sl1 = sl0 + 2;
        #pragma unroll
        for (int kk = 0; kk < 8; kk++) {
            float u00 = __shfl_sync(0xffffffffu, s[kk][0], sl0);
            float u01 = __shfl_sync(0xffffffffu, s[kk][1], sl0);
            float u02 = __shfl_sync(0xffffffffu, s[kk][0], sl1);
            float u03 = __shfl_sync(0xffffffffu, s[kk][1], sl1);
            float u10 = __shfl_sync(0xffffffffu, s[kk][2], sl0);
            float u11 = __shfl_sync(0xffffffffu, s[kk][3], sl0);
            float u12 = __shfl_sync(0xffffffffu, s[kk][2], sl1);
            float u13 = __shfl_sync(0xffffffffu, s[kk][3], sl1);
            uint32_t af[4];
            af[0] = f2tf((tig & 1) ? u01 : u00);
            af[1] = f2tf((tig & 1) ? u11 : u10);
            af[2] = f2tf((tig & 1) ? u03 : u02);
            af[3] = f2tf((tig & 1) ? u13 : u12);
            #pragma unroll
            for (int nt = 0; nt < 8; nt++) {
                uint32_t bf[2];
                bf[0] = sV[(kk * 8 + tig)     * SVS + nt * 8 + gid];
                bf[1] = sV[(kk * 8 + tig + 4) * SVS + nt * 8 + gid];
                mma_tf32(oacc[nt], af, bf);
            }
        }
        __syncthreads();
    }

    float inv0 = 1.f / l0, inv1 = 1.f / l1;
    float* o0 = out + ((long long)(b * SEQ + row0)) * EDIM + h * DHD;
    float* o1 = out + ((long long)(b * SEQ + row1)) * EDIM + h * DHD;
    #pragma unroll
    for (int nt = 0; nt < 8; nt++) {
        int c = nt * 8 + 2 * tig;
        *(float2*)(o0 + c) = make_float2(tfr(oacc[nt][0] * inv0), tfr(oacc[nt][1] * inv0));
        *(float2*)(o1 + c) = make_float2(tfr(oacc[nt][2] * inv1), tfr(oacc[nt][3] * inv1));
    }
}

// ---------------- fused residual + LayerNorm (in-place, + rounded copy) -----
__global__ void ln_res_k(float* __restrict__ x, const float* __restrict__ d,
                         const float* __restrict__ g, const float* __restrict__ b,
                         float* __restrict__ xr)
{
    long long row = blockIdx.x;
    float* xp = x + row * EDIM;
    const float* dr = d + row * EDIM;
    int t = threadIdx.x;
    float4 xv = ((float4*)xp)[t];
    float4 dv = ((const float4*)dr)[t];
    float v0 = xv.x + dv.x, v1 = xv.y + dv.y, v2 = xv.z + dv.z, v3 = xv.w + dv.w;
    float mean = blockReduceSum(v0 + v1 + v2 + v3) * (1.f / EDIM);
    float c0 = v0 - mean, c1 = v1 - mean, c2 = v2 - mean, c3 = v3 - mean;
    float var = blockReduceSum(c0 * c0 + c1 * c1 + c2 * c2 + c3 * c3) * (1.f / EDIM);
    float rstd = rsqrtf(var + 1e-5f);
    float4 gv = ((const float4*)g)[t];
    float4 bv = ((const float4*)b)[t];
    float4 o = make_float4(c0 * rstd * gv.x + bv.x, c1 * rstd * gv.y + bv.y,
                           c2 * rstd * gv.z + bv.z, c3 * rstd * gv.w + bv.w);
    ((float4*)xp)[t] = o;
    ((float4*)(xr + row * EDIM))[t] = make_float4(tfr(o.x), tfr(o.y), tfr(o.z), tfr(o.w));
}

// ---------------- host-side launch helpers ----------------------------------
#define STGN 5
static inline int smemMain() { return STGN * (128 * 12 + 8 * 136) * 4; }   // 52,480 B
static inline int smemTall() { return STGN * ( 64 * 12 + 8 * 136) * 4; }   // 37,120 B

template<int bMode>
static inline void gMain(const float* A, const float* Bm, const float* bias, float* C,
                         int M, int N, int K, int lda, int ldb, int ldc,
                         int cMode, int relu, int rOut, int nOff, float scale)
{
    dim3 grid(N / 128, M / 128, 1);
    tmma_k<128, 128, 8, STGN, 4, 4, 4, bMode><<<grid, 256, smemMain()>>>(
        A, Bm, bias, C, M, N, K, lda, ldb, ldc, cMode, relu, rOut, nOff, scale);
}
template<int bMode>
static inline void gTall(const float* A, const float* Bm, const float* bias, float* C,
                         int M, int N, int K, int lda, int ldb, int ldc,
                         int cMode, int relu, int rOut, int nOff, float scale)
{
    dim3 grid(N / 128, M / 64, 1);
    tmma_k<64, 128, 8, STGN, 4, 2, 4, bMode><<<grid, 256, smemTall()>>>(
        A, Bm, bias, C, M, N, K, lda, ldb, ldc, cMode, relu, rOut, nOff, scale);
}

// attention core after q/k/v are in g_qkv; t1 written pre-rounded by flash
static void attn_core(float* qkv, float* t1, float* t2,
                      const float* wo, const float* bo,
                      const float* pad, int causal)
{
    float* q = qkv;
    float* k = qkv + QKVOFF;
    float* v = qkv + 2 * QKVOFF;
    dim3 fg(SEQ / 128, NBH);
    if (causal) flash_k<1><<<fg, 256>>>(q, k, v, pad, t1);
    else        flash_k<0><<<fg, 256>>>(q, k, v, pad, t1);
    gTall<0>(t1, wo, bo, t2, NROWS, EDIM, EDIM, EDIM, EDIM, EDIM, 0, 0, 0, 0, 1.f);
}

static void ffn_block(float* x, float* xr, const float* w1, const float* b1,
                      const float* w2, const float* b2,
                      const float* lg, const float* lb, float* ff, float* t2)
{
    gMain<0>(xr, w1, b1, ff, NROWS, DFFD, EDIM, EDIM, DFFD, DFFD, 0, 1, 1, 0, 1.f);
    gTall<0>(ff, w2, b2, t2, NROWS, EDIM, DFFD, DFFD, EDIM, EDIM, 0, 0, 0, 0, 1.f);
    ln_res_k<<<NROWS, 256>>>(x, t2, lg, lb, xr);
}

// ---------------- entry -----------------------------------------------------
extern "C" void kernel_launch(void* const* d_in, const int* in_sizes, int n_in,
                              void* d_out, int out_size)
{
    const float* src      = (const float*)d_in[0];
    const float* tgt      = (const float*)d_in[1];
    const float* src_pad  = (const float*)d_in[4];
    const float* tgt_pad  = (const float*)d_in[5];
    const float* enc_wqkv = (const float*)d_in[6];
    const float* enc_wo   = (const float*)d_in[7];
    const float* enc_bo   = (const float*)d_in[8];
    const float* enc_w1   = (const float*)d_in[9];
    const float* enc_b1   = (const float*)d_in[10];
    const float* enc_w2   = (const float*)d_in[11];
    const float* enc_b2   = (const float*)d_in[12];
    const float* enc_lg   = (const float*)d_in[13];
    const float* enc_lb   = (const float*)d_in[14];
    const float* dqkv_s   = (const float*)d_in[15];
    const float* dwo_s    = (const float*)d_in[16];
    const float* dbo_s    = (const float*)d_in[17];
    const float* dqkv_c   = (const float*)d_in[18];
    const float* dwo_c    = (const float*)d_in[19];
    const float* dbo_c    = (const float*)d_in[20];
    const float* dw1      = (const float*)d_in[21];
    const float* db1      = (const float*)d_in[22];
    const float* dw2      = (const float*)d_in[23];
    const float* db2      = (const float*)d_in[24];
    const float* dlg      = (const float*)d_in[25];
    const float* dlb      = (const float*)d_in[26];

    // one-time (idempotent) dynamic smem opt-in for >48KB
    cudaFuncSetAttribute((const void*)tmma_k<128,128,8,STGN,4,4,4,0>,
                         cudaFuncAttributeMaxDynamicSharedMemorySize, smemMain());
    cudaFuncSetAttribute((const void*)tmma_k<128,128,8,STGN,4,4,4,1>,
                         cudaFuncAttributeMaxDynamicSharedMemorySize, smemMain());
    cudaFuncSetAttribute((const void*)tmma_k<64,128,8,STGN,4,2,4,0>,
                         cudaFuncAttributeMaxDynamicSharedMemorySize, smemTall());
    cudaFuncSetAttribute((const void*)tmma_k<64,128,8,STGN,4,2,4,1>,
                         cudaFuncAttributeMaxDynamicSharedMemorySize, smemTall());

    float *x, *y, *xr, *yr, *qkv, *t1, *t2, *ff, *wtf;
    cudaGetSymbolAddress((void**)&x,   g_x);
    cudaGetSymbolAddress((void**)&y,   g_y);
    cudaGetSymbolAddress((void**)&xr,  g_xr);
    cudaGetSymbolAddress((void**)&yr,  g_yr);
    cudaGetSymbolAddress((void**)&qkv, g_qkv);
    cudaGetSymbolAddress((void**)&t1,  g_t1);
    cudaGetSymbolAddress((void**)&t2,  g_t2);
    cudaGetSymbolAddress((void**)&ff,  g_ff);
    cudaGetSymbolAddress((void**)&wtf, g_wtf);

    dim3 tg(SEQ, NB);
    reorder_k<<<tg, 256>>>(src, x, xr, 1);                       // launch 0
    reorder_k<<<tg, 256>>>(tgt, y, yr, 1);                       // launch 1
    roundcopy_all_k<<<2048, 256>>>(enc_wqkv, enc_wo, enc_w1, enc_w2,
                                   dqkv_s, dwo_s, dqkv_c, dwo_c,
                                   dw1, dw2, wtf);               // launch 2

    const long long WL = (long long)3 * HN * EDIM * DHD;  // per-layer wqkv slab
    const long long WS = (long long)HN * EDIM * DHD;      // one of q/k/v
    const long long WO = (long long)EDIM * EDIM;
    const long long W1 = (long long)EDIM * DFFD;

    for (int l = 0; l < NLE; l++) {
        // launch 3 (l=0): the representative big GEMM — profiled by ncu
        gMain<1>(xr, wtf + W_EQKV + l * WL, nullptr, qkv, NROWS, 3 * EDIM, EDIM,
                 EDIM, 0, 0, 1, 0, 0, 0, 1.f);
        attn_core(qkv, t1, t2, wtf + W_EWO + l * WO, enc_bo + l * EDIM, src_pad, 0);
        ln_res_k<<<NROWS, 256>>>(x, t2, enc_lg + (l * 2 + 0) * EDIM,
                                 enc_lb + (l * 2 + 0) * EDIM, xr);
        ffn_block(x, xr, wtf + W_EW1 + l * W1, enc_b1 + l * DFFD,
                  wtf + W_EW2 + l * W1, enc_b2 + l * EDIM,
                  enc_lg + (l * 2 + 1) * EDIM, enc_lb + (l * 2 + 1) * EDIM, ff, t2);
    }

    for (int l = 0; l < NLD; l++) {
        gMain<1>(yr, wtf + W_DQS + l * WL, nullptr, qkv, NROWS, 3 * EDIM, EDIM,
                 EDIM, 0, 0, 1, 0, 0, 0, 1.f);
        attn_core(qkv, t1, t2, wtf + W_DWOS + l * WO, dbo_s + l * EDIM, tgt_pad, 1);
        ln_res_k<<<NROWS, 256>>>(y, t2, dlg + (l * 3 + 0) * EDIM,
                                 dlb + (l * 3 + 0) * EDIM, yr);

        gTall<1>(yr, wtf + W_DQC + l * WL, nullptr, qkv, NROWS, EDIM, EDIM,
                 EDIM, 0, 0, 1, 0, 0, 0, 1.f);
        gMain<1>(xr, wtf + W_DQC + l * WL + WS, nullptr, qkv, NROWS, 2 * EDIM, EDIM,
                 EDIM, 0, 0, 1, 0, 0, 1024, 1.f);
        attn_core(qkv, t1, t2, wtf + W_DWOC + l * WO, dbo_c + l * EDIM, src_pad, 0);
        ln_res_k<<<NROWS, 256>>>(y, t2, dlg + (l * 3 + 1) * EDIM,
                                 dlb + (l * 3 + 1) * EDIM, yr);

        ffn_block(y, yr, wtf + W_DW1 + l * W1, db1 + l * DFFD,
                  wtf + W_DW2 + l * W1, db2 + l * EDIM,
                  dlg + (l * 3 + 2) * EDIM, dlb + (l * 3 + 2) * EDIM, ff, t2);
    }

    reorder_k<<<tg, 256>>>(y, (float*)d_out, nullptr, 0);
}